// round 16
// baseline (speedup 1.0000x reference)
#include <cuda_runtime.h>
#include <math.h>
#include <stdint.h>

// Problem constants
#define SEQ   512
#define BATCH 64
#define HID   1024
#define NIN   512
#define NOUT  512
#define BH    (BATCH * HID)
// Recurrence grid: 8 jt (128 cols) x 8 kc (128 k) x 2 bh (32 rows) = 128 CTAs
#define NKC   8

// Scratch (device globals). Layout of xi/h: [s][b][h]
__device__ float g_xi[(size_t)SEQ * BATCH * HID];
__device__ float g_h [(size_t)SEQ * BATCH * HID];
// Partials, parity double-buffered: [par][q 8][64 rows][1024 cols]
__device__ float g_part[2][NKC][BATCH][HID];

// Dataflow counters (padded 128B apart; reset node before each replay)
__device__ unsigned g_grp [16 * 32];     // phase-A completions per (jt,bh)
__device__ unsigned g_done[16 * 32];     // phase-B completions per (jt,bh)
__device__ unsigned g_xidone[4 * 32];    // GEMM1 s-block progress (target 512)

__global__ void reset_barriers()
{
    if (threadIdx.x < 16) {
        g_grp [threadIdx.x << 5] = 0;
        g_done[threadIdx.x << 5] = 0;
    }
    if (threadIdx.x < 4)
        g_xidone[threadIdx.x << 5] = 0;
}

__device__ __forceinline__ unsigned ld_acq(const unsigned* p)
{
    unsigned v;
    asm volatile("ld.acquire.gpu.global.u32 %0, [%1];" : "=r"(v) : "l"(p));
    return v;
}
__device__ __forceinline__ void arrive(unsigned* p)
{
    asm volatile("red.release.gpu.global.add.u32 [%0], 1;" :: "l"(p) : "memory");
}

// ---------------------------------------------------------------------------
// 128x128x8 fp32 SGEMM with bias + output-row permutation (proven, ~roofline)
// PERM=1: A row m=(b*512+s) -> C row (s*64+b)   [GEMM1: x->xi]
// PERM=2: A row m=(s*64+b)  -> C row (b*512+s)  [GEMM3: h->y]
// PROG=1: y-tiles remapped s-major + arrive g_xidone[sb] when tile stored.
// ---------------------------------------------------------------------------
template<int K, int N, int PERM, int PROG>
__global__ __launch_bounds__(256, 2) void gemm128(
    const float* __restrict__ A, const float* __restrict__ Bm,
    const float* __restrict__ bias, float* __restrict__ C)
{
    __shared__ float As[8][132];
    __shared__ float Bs[8][128];

    const int tid = threadIdx.x;
    const int tx = tid & 15, ty = tid >> 4;
    const int byl = blockIdx.y;
    const int byp = PROG ? (((byl & 63) << 2) | (byl >> 6)) : byl;
    const int row0 = byp * 128, col0 = blockIdx.x * 128;

    const int a_r = tid >> 1, a_k = (tid & 1) << 2;
    const int b_k = tid >> 5, b_c = (tid & 31) << 2;

    const float* Ap = A + (size_t)(row0 + a_r) * K + a_k;
    const float* Bp = Bm + (size_t)b_k * N + col0 + b_c;

    float4 ar = *(const float4*)Ap;
    float4 br = *(const float4*)Bp;

    float acc[8][8] = {};

    for (int k0 = 0; k0 < K; k0 += 8) {
        As[a_k + 0][a_r] = ar.x;
        As[a_k + 1][a_r] = ar.y;
        As[a_k + 2][a_r] = ar.z;
        As[a_k + 3][a_r] = ar.w;
        *(float4*)&Bs[b_k][b_c] = br;
        __syncthreads();
        if (k0 + 8 < K) {
            ar = *(const float4*)(Ap + k0 + 8);
            br = *(const float4*)(Bp + (size_t)(k0 + 8) * N);
        }
#pragma unroll
        for (int kk = 0; kk < 8; kk++) {
            float4 a0 = *(const float4*)&As[kk][ty << 2];
            float4 a1 = *(const float4*)&As[kk][(ty << 2) + 64];
            float4 b0 = *(const float4*)&Bs[kk][tx << 2];
            float4 b1 = *(const float4*)&Bs[kk][(tx << 2) + 64];
            float av[8] = {a0.x, a0.y, a0.z, a0.w, a1.x, a1.y, a1.z, a1.w};
            float bv[8] = {b0.x, b0.y, b0.z, b0.w, b1.x, b1.y, b1.z, b1.w};
#pragma unroll
            for (int i = 0; i < 8; i++)
#pragma unroll
                for (int j = 0; j < 8; j++)
                    acc[i][j] = fmaf(av[i], bv[j], acc[i][j]);
        }
        __syncthreads();
    }

    float4 bb0 = *(const float4*)&bias[col0 + (tx << 2)];
    float4 bb1 = *(const float4*)&bias[col0 + (tx << 2) + 64];
#pragma unroll
    for (int i = 0; i < 8; i++) {
        const int mloc = (i < 4) ? ((ty << 2) + i) : ((ty << 2) + i + 60);
        const int m = row0 + mloc;
        size_t r;
        if (PERM == 1)      r = (size_t)((m & 511) * 64 + (m >> 9));
        else if (PERM == 2) r = (size_t)((m & 63) * 512 + (m >> 6));
        else                r = (size_t)m;
        float* Cr = C + r * N + col0;
        float4 o0 = make_float4(acc[i][0] + bb0.x, acc[i][1] + bb0.y,
                                acc[i][2] + bb0.z, acc[i][3] + bb0.w);
        float4 o1 = make_float4(acc[i][4] + bb1.x, acc[i][5] + bb1.y,
                                acc[i][6] + bb1.z, acc[i][7] + bb1.w);
        *(float4*)(Cr + (tx << 2)) = o0;
        *(float4*)(Cr + (tx << 2) + 64) = o1;
    }

    if (PROG) {
        __syncthreads();
        if (tid == 0) arrive(&g_xidone[(byl >> 6) << 5]);
    }
}

// ---------------------------------------------------------------------------
// Persistent recurrence (round-14 config: best measured) + xi progress gates.
// CTA = (jt, kc, bh): jt=bx&7 cols[128jt), kc=(bx>>3)&7 k[128kc), bh=bx>>6
// rows[32bh). Wh slice [128k][128j] smem-resident (64KB).
// ---------------------------------------------------------------------------
#define RNN_DSMEM ((16384 + 16 * 36) * 4)

__global__ __launch_bounds__(128) void rnn_recurrence(const float* __restrict__ Wh)
{
    extern __shared__ float dsm[];
    float* Bs = dsm;                 // [128 k][128 j]
    float* As = dsm + 16384;         // [16 k][36 rows]

    const int tid = threadIdx.x;
    const int jt = blockIdx.x & 7;
    const int kc = (blockIdx.x >> 3) & 7;
    const int bhh = blockIdx.x >> 6;
    const int col0 = jt << 7;
    const int kbase = kc << 7;
    const int rbase = bhh << 5;
    const int w  = tid >> 5;
    const int tx = tid & 31;
    const int a_r = tid >> 2, a_k = (tid & 3) << 2;
    const int own = ((jt << 1) | bhh) << 5;
    const int src = ((kc << 1) | bhh) << 5;

    // Load persistent Wh slice [128k][128j] (one-time, 64KB)
#pragma unroll
    for (int i = 0; i < 32; i++) {
        const int e4 = i * 128 + tid;
        const int k = e4 >> 5, c = (e4 & 31) << 2;
        *(float4*)&Bs[k * 128 + c] =
            *(const float4*)&Wh[(size_t)(kbase + k) * HID + col0 + c];
    }

    // Gate on xi s-block 0 (GEMM1 running concurrently)
    while (ld_acq(&g_xidone[0]) < 512u) {}

    // h_0 init on this CTA's phase-B slice
    {
        const int row = rbase + (kc << 2) + w;
        const int cc = col0 + (tx << 2);
        const size_t off = (size_t)row * HID + cc;
        float4 v = *(const float4*)&g_xi[off];
        v.x = fmaxf(tanhf(v.x), 0.0f);
        v.y = fmaxf(tanhf(v.y), 0.0f);
        v.z = fmaxf(tanhf(v.z), 0.0f);
        v.w = fmaxf(tanhf(v.w), 0.0f);
        *(float4*)&g_h[off] = v;
    }
    __syncthreads();
    if (tid == 0) arrive(&g_done[own]);

    for (int t = 1; t < SEQ; t++) {
        const unsigned target = 8u * (unsigned)t;

        // Gate on xi s-block when crossing a 128-step boundary
        if ((t & 127) == 0) {
            while (ld_acq(&g_xidone[(t >> 7) << 5]) < 512u) {}
        }

        // ---- A-wait: h(t-1) rows[rbase..+32) cols[kbase..+128) ready ----
        while (ld_acq(&g_done[src]) < target) {}

        // ---- phase A: 32x128 partial GEMM over 128-wide K chunk ----
        const float* hprev = g_h + (size_t)(t - 1) * BH;
        float acc[8][4] = {};

        const float* hrow = hprev + (size_t)(rbase + a_r) * HID + kbase + a_k;
        float4 pa = *(const float4*)hrow;

        for (int k0 = 0; k0 < 128; k0 += 16) {
            As[(a_k + 0) * 36 + a_r] = pa.x;
            As[(a_k + 1) * 36 + a_r] = pa.y;
            As[(a_k + 2) * 36 + a_r] = pa.z;
            As[(a_k + 3) * 36 + a_r] = pa.w;
            __syncthreads();
            if (k0 + 16 < 128)
                pa = *(const float4*)(hrow + k0 + 16);
#pragma unroll
            for (int kk = 0; kk < 16; kk++) {
                float4 a0 = *(const float4*)&As[kk * 36 + (w << 3)];
                float4 a1 = *(const float4*)&As[kk * 36 + (w << 3) + 4];
                float4 b  = *(const float4*)&Bs[(k0 + kk) * 128 + (tx << 2)];
                float av[8] = {a0.x, a0.y, a0.z, a0.w, a1.x, a1.y, a1.z, a1.w};
                float bv[4] = {b.x, b.y, b.z, b.w};
#pragma unroll
                for (int i = 0; i < 8; i++)
#pragma unroll
                    for (int j = 0; j < 4; j++)
                        acc[i][j] = fmaf(av[i], bv[j], acc[i][j]);
            }
            __syncthreads();
        }

        // store partials: rows rbase + w*8 + i, cols col0 + tx*4
        {
            float* pd = &g_part[t & 1][kc][0][0];
#pragma unroll
            for (int i = 0; i < 8; i++) {
                const int row = rbase + (w << 3) + i;
                *(float4*)&pd[(size_t)row * HID + col0 + (tx << 2)] =
                    make_float4(acc[i][0], acc[i][1], acc[i][2], acc[i][3]);
            }
        }
        __syncthreads();
        if (tid == 0) arrive(&g_grp[own]);

        // ---- phase B: reduce own 4-row slice from 8 partials ----
        {
            const int row = rbase + (kc << 2) + w;
            const int cc = col0 + (tx << 2);
            const size_t eo = (size_t)row * HID + cc;
            const size_t off = (size_t)t * BH + eo;
            float4 v = *(const float4*)&g_xi[off];   // prefetch before wait

            while (ld_acq(&g_grp[own]) < target) {}

            const float* pt = &g_part[t & 1][0][0][0];
#pragma unroll
            for (int q = 0; q < NKC; q++) {
                float4 p = *(const float4*)&pt[(size_t)q * BH + eo];
                v.x += p.x; v.y += p.y; v.z += p.z; v.w += p.w;
            }
            v.x = fmaxf(tanhf(v.x), 0.0f);
            v.y = fmaxf(tanhf(v.y), 0.0f);
            v.z = fmaxf(tanhf(v.z), 0.0f);
            v.w = fmaxf(tanhf(v.w), 0.0f);
            *(float4*)&g_h[off] = v;
        }
        __syncthreads();
        if (tid == 0) arrive(&g_done[own]);
    }
}

// ---------------------------------------------------------------------------
extern "C" void kernel_launch(void* const* d_in, const int* in_sizes, int n_in,
                              void* d_out, int out_size)
{
    const float* x  = (const float*)d_in[0];
    const float* Wi = (const float*)d_in[1];
    const float* bi = (const float*)d_in[2];
    const float* Wh = (const float*)d_in[3];
    const float* Wo = (const float*)d_in[4];
    const float* bo = (const float*)d_in[5];
    float* out = (float*)d_out;

    void* p;
    cudaGetSymbolAddress(&p, g_xi);
    float* xi = (float*)p;
    cudaGetSymbolAddress(&p, g_h);
    float* hh = (float*)p;

    // One-time infra (created on the first, non-captured, correctness call)
    static cudaStream_t s2 = nullptr;
    static cudaEvent_t evFork = nullptr, evJoin = nullptr;
    if (s2 == nullptr) {
        cudaStreamCreateWithFlags(&s2, cudaStreamNonBlocking);
        cudaEventCreateWithFlags(&evFork, cudaEventDisableTiming);
        cudaEventCreateWithFlags(&evJoin, cudaEventDisableTiming);
    }

    cudaFuncSetAttribute(rnn_recurrence,
                         cudaFuncAttributeMaxDynamicSharedMemorySize, RNN_DSMEM);

    // 0) zero dataflow counters (default stream; ordered before both branches)
    reset_barriers<<<1, 32>>>();

    // Fork: GEMM1 on side stream, recurrence on default stream (concurrent).
    cudaEventRecord(evFork, 0);
    cudaStreamWaitEvent(s2, evFork, 0);

    // 1) xi[s][b][h] = x @ Wi + bi  — s-major tile order + progress counters
    gemm128<NIN, HID, 1, 1>
        <<<dim3(HID / 128, (BATCH * SEQ) / 128), 256, 0, s2>>>(x, Wi, bi, xi);

    // 2) recurrence (gates on g_xidone per s-block; round-14 proven core)
    rnn_recurrence<<<128, 128, RNN_DSMEM>>>(Wh);

    // Join side stream before GEMM3
    cudaEventRecord(evJoin, s2);
    cudaStreamWaitEvent(0, evJoin, 0);

    // 3) y[b][s][o] = h @ Wo + bo    (fp32, ~roofline)
    gemm128<HID, NOUT, 2, 0>
        <<<dim3(NOUT / 128, (BATCH * SEQ) / 128), 256>>>(hh, Wo, bo, out);
}

// round 17
// speedup vs baseline: 1.4796x; 1.4796x over previous
#include <cuda_runtime.h>
#include <math.h>
#include <stdint.h>

// Problem constants
#define SEQ   512
#define BATCH 64
#define HID   1024
#define NIN   512
#define NOUT  512
#define BH    (BATCH * HID)
// Recurrence grid: 8 jt (128 cols) x 8 kc (128 k) x 2 bh (32 rows) = 128 CTAs
#define NKC   8

// Scratch (device globals). Layout of xi/h: [s][b][h]
__device__ float g_xi[(size_t)SEQ * BATCH * HID];
__device__ float g_h [(size_t)SEQ * BATCH * HID];
// Partials, parity double-buffered: [par][q 8][64 rows][1024 cols]
__device__ float g_part[2][NKC][BATCH][HID];

// Dataflow counters, one per (jt,bh) group, padded 128B apart.
// Warp-granular arrives: 8 CTAs x 4 warps = 32 arrives per step per counter.
__device__ unsigned g_grp [16 * 32];
__device__ unsigned g_done[16 * 32];

__global__ void reset_barriers()
{
    if (threadIdx.x < 16) {
        g_grp [threadIdx.x << 5] = 0;
        g_done[threadIdx.x << 5] = 0;
    }
}

__device__ __forceinline__ unsigned ld_acq(const unsigned* p)
{
    unsigned v;
    asm volatile("ld.acquire.gpu.global.u32 %0, [%1];" : "=r"(v) : "l"(p));
    return v;
}
__device__ __forceinline__ void arrive(unsigned* p)
{
    asm volatile("red.release.gpu.global.add.u32 [%0], 1;" :: "l"(p) : "memory");
}

// ---------------------------------------------------------------------------
// 128x128x8 fp32 SGEMM with bias + output-row permutation (proven, ~roofline)
// PERM=1: A row m=(b*512+s) -> C row (s*64+b)   [GEMM1: x->xi]
// PERM=2: A row m=(s*64+b)  -> C row (b*512+s)  [GEMM3: h->y]
// ---------------------------------------------------------------------------
template<int K, int N, int PERM>
__global__ __launch_bounds__(256, 2) void gemm128(
    const float* __restrict__ A, const float* __restrict__ Bm,
    const float* __restrict__ bias, float* __restrict__ C)
{
    __shared__ float As[8][132];
    __shared__ float Bs[8][128];

    const int tid = threadIdx.x;
    const int tx = tid & 15, ty = tid >> 4;
    const int row0 = blockIdx.y * 128, col0 = blockIdx.x * 128;

    const int a_r = tid >> 1, a_k = (tid & 1) << 2;
    const int b_k = tid >> 5, b_c = (tid & 31) << 2;

    const float* Ap = A + (size_t)(row0 + a_r) * K + a_k;
    const float* Bp = Bm + (size_t)b_k * N + col0 + b_c;

    float4 ar = *(const float4*)Ap;
    float4 br = *(const float4*)Bp;

    float acc[8][8] = {};

    for (int k0 = 0; k0 < K; k0 += 8) {
        As[a_k + 0][a_r] = ar.x;
        As[a_k + 1][a_r] = ar.y;
        As[a_k + 2][a_r] = ar.z;
        As[a_k + 3][a_r] = ar.w;
        *(float4*)&Bs[b_k][b_c] = br;
        __syncthreads();
        if (k0 + 8 < K) {
            ar = *(const float4*)(Ap + k0 + 8);
            br = *(const float4*)(Bp + (size_t)(k0 + 8) * N);
        }
#pragma unroll
        for (int kk = 0; kk < 8; kk++) {
            float4 a0 = *(const float4*)&As[kk][ty << 2];
            float4 a1 = *(const float4*)&As[kk][(ty << 2) + 64];
            float4 b0 = *(const float4*)&Bs[kk][tx << 2];
            float4 b1 = *(const float4*)&Bs[kk][(tx << 2) + 64];
            float av[8] = {a0.x, a0.y, a0.z, a0.w, a1.x, a1.y, a1.z, a1.w};
            float bv[8] = {b0.x, b0.y, b0.z, b0.w, b1.x, b1.y, b1.z, b1.w};
#pragma unroll
            for (int i = 0; i < 8; i++)
#pragma unroll
                for (int j = 0; j < 8; j++)
                    acc[i][j] = fmaf(av[i], bv[j], acc[i][j]);
        }
        __syncthreads();
    }

    float4 bb0 = *(const float4*)&bias[col0 + (tx << 2)];
    float4 bb1 = *(const float4*)&bias[col0 + (tx << 2) + 64];
#pragma unroll
    for (int i = 0; i < 8; i++) {
        const int mloc = (i < 4) ? ((ty << 2) + i) : ((ty << 2) + i + 60);
        const int m = row0 + mloc;
        size_t r;
        if (PERM == 1)      r = (size_t)((m & 511) * 64 + (m >> 9));
        else if (PERM == 2) r = (size_t)((m & 63) * 512 + (m >> 6));
        else                r = (size_t)m;
        float* Cr = C + r * N + col0;
        float4 o0 = make_float4(acc[i][0] + bb0.x, acc[i][1] + bb0.y,
                                acc[i][2] + bb0.z, acc[i][3] + bb0.w);
        float4 o1 = make_float4(acc[i][4] + bb1.x, acc[i][5] + bb1.y,
                                acc[i][6] + bb1.z, acc[i][7] + bb1.w);
        *(float4*)(Cr + (tx << 2)) = o0;
        *(float4*)(Cr + (tx << 2) + 64) = o1;
    }
}

// ---------------------------------------------------------------------------
// Persistent recurrence (round-14 topology) with warp-scope publication.
// CTA = (jt, kc, bh): jt=bx&7 cols[128jt), kc=(bx>>3)&7 k[128kc), bh=bx>>6
// rows[32bh). Wh slice [128k][128j] smem-resident (64KB).
// Phase A partial slices and phase B h-rows are warp-contained, so each warp
// publishes its own work: __syncwarp + lane-0 release-arrive (targets 32t).
// Trailing CTA barriers removed; the first staging __syncthreads of the next
// k-loop re-protects As.
// ---------------------------------------------------------------------------
#define RNN_DSMEM ((16384 + 16 * 36) * 4)

__global__ __launch_bounds__(128) void rnn_recurrence(const float* __restrict__ Wh)
{
    extern __shared__ float dsm[];
    float* Bs = dsm;                 // [128 k][128 j]
    float* As = dsm + 16384;         // [16 k][36 rows] (144B rows, 16B-aligned)

    const int tid = threadIdx.x;
    const int lane = tid & 31;
    const int jt = blockIdx.x & 7;
    const int kc = (blockIdx.x >> 3) & 7;
    const int bhh = blockIdx.x >> 6;
    const int col0 = jt << 7;
    const int kbase = kc << 7;
    const int rbase = bhh << 5;
    const int w  = tid >> 5;                 // warp 0..3
    const int tx = tid & 31;
    const int a_r = tid >> 2, a_k = (tid & 3) << 2;
    const int own = ((jt << 1) | bhh) << 5;
    const int src = ((kc << 1) | bhh) << 5;

    // Load persistent Wh slice [128k][128j] (one-time, 64KB).
    // Visibility to other warps is covered by the first in-loop __syncthreads.
#pragma unroll
    for (int i = 0; i < 32; i++) {
        const int e4 = i * 128 + tid;
        const int k = e4 >> 5, c = (e4 & 31) << 2;
        *(float4*)&Bs[k * 128 + c] =
            *(const float4*)&Wh[(size_t)(kbase + k) * HID + col0 + c];
    }

    // h_0 init on this CTA's phase-B slice (one row per warp), warp-publish
    {
        const int row = rbase + (kc << 2) + w;
        const int cc = col0 + (tx << 2);
        const size_t off = (size_t)row * HID + cc;
        float4 v = *(const float4*)&g_xi[off];
        v.x = fmaxf(tanhf(v.x), 0.0f);
        v.y = fmaxf(tanhf(v.y), 0.0f);
        v.z = fmaxf(tanhf(v.z), 0.0f);
        v.w = fmaxf(tanhf(v.w), 0.0f);
        *(float4*)&g_h[off] = v;
        __syncwarp();
        if (lane == 0) arrive(&g_done[own]);
    }

    for (int t = 1; t < SEQ; t++) {
        const unsigned target = 32u * (unsigned)t;

        // ---- A-wait: h(t-1) rows[rbase..+32) cols[kbase..+128) ready ----
        while (ld_acq(&g_done[src]) < target) {}

        // ---- phase A: 32x128 partial GEMM over 128-wide K chunk ----
        const float* hprev = g_h + (size_t)(t - 1) * BH;
        float acc[8][4] = {};

        const float* hrow = hprev + (size_t)(rbase + a_r) * HID + kbase + a_k;
        float4 pa = *(const float4*)hrow;

        for (int k0 = 0; k0 < 128; k0 += 16) {
            As[(a_k + 0) * 36 + a_r] = pa.x;
            As[(a_k + 1) * 36 + a_r] = pa.y;
            As[(a_k + 2) * 36 + a_r] = pa.z;
            As[(a_k + 3) * 36 + a_r] = pa.w;
            __syncthreads();
            if (k0 + 16 < 128)
                pa = *(const float4*)(hrow + k0 + 16);
#pragma unroll
            for (int kk = 0; kk < 16; kk++) {
                float4 a0 = *(const float4*)&As[kk * 36 + (w << 3)];
                float4 a1 = *(const float4*)&As[kk * 36 + (w << 3) + 4];
                float4 b  = *(const float4*)&Bs[(k0 + kk) * 128 + (tx << 2)];
                float av[8] = {a0.x, a0.y, a0.z, a0.w, a1.x, a1.y, a1.z, a1.w};
                float bv[4] = {b.x, b.y, b.z, b.w};
#pragma unroll
                for (int i = 0; i < 8; i++)
#pragma unroll
                    for (int j = 0; j < 4; j++)
                        acc[i][j] = fmaf(av[i], bv[j], acc[i][j]);
            }
            if (k0 + 16 < 128) __syncthreads();
            // (no trailing barrier on last tile: stores below use registers
            // only; As is re-protected by next staging's __syncthreads)
        }

        // store partials (warp-contained rows) and warp-publish
        {
            float* pd = &g_part[t & 1][kc][0][0];
#pragma unroll
            for (int i = 0; i < 8; i++) {
                const int row = rbase + (w << 3) + i;
                *(float4*)&pd[(size_t)row * HID + col0 + (tx << 2)] =
                    make_float4(acc[i][0], acc[i][1], acc[i][2], acc[i][3]);
            }
            __syncwarp();
            if (lane == 0) arrive(&g_grp[own]);
        }

        // ---- phase B: reduce own row (warp-contained) from 8 partials ----
        {
            const int row = rbase + (kc << 2) + w;
            const int cc = col0 + (tx << 2);
            const size_t eo = (size_t)row * HID + cc;
            const size_t off = (size_t)t * BH + eo;
            float4 v = *(const float4*)&g_xi[off];   // prefetch before wait

            while (ld_acq(&g_grp[own]) < target) {}

            const float* pt = &g_part[t & 1][0][0][0];
#pragma unroll
            for (int q = 0; q < NKC; q++) {
                float4 p = *(const float4*)&pt[(size_t)q * BH + eo];
                v.x += p.x; v.y += p.y; v.z += p.z; v.w += p.w;
            }
            v.x = fmaxf(tanhf(v.x), 0.0f);
            v.y = fmaxf(tanhf(v.y), 0.0f);
            v.z = fmaxf(tanhf(v.z), 0.0f);
            v.w = fmaxf(tanhf(v.w), 0.0f);
            *(float4*)&g_h[off] = v;
            __syncwarp();
            if (lane == 0) arrive(&g_done[own]);
        }
    }
}

// ---------------------------------------------------------------------------
extern "C" void kernel_launch(void* const* d_in, const int* in_sizes, int n_in,
                              void* d_out, int out_size)
{
    const float* x  = (const float*)d_in[0];
    const float* Wi = (const float*)d_in[1];
    const float* bi = (const float*)d_in[2];
    const float* Wh = (const float*)d_in[3];
    const float* Wo = (const float*)d_in[4];
    const float* bo = (const float*)d_in[5];
    float* out = (float*)d_out;

    void* p;
    cudaGetSymbolAddress(&p, g_xi);
    float* xi = (float*)p;
    cudaGetSymbolAddress(&p, g_h);
    float* hh = (float*)p;

    cudaFuncSetAttribute(rnn_recurrence,
                         cudaFuncAttributeMaxDynamicSharedMemorySize, RNN_DSMEM);

    // 0) zero dataflow counters so every graph replay starts clean
    reset_barriers<<<1, 32>>>();

    // 1) xi[s][b][h] = x @ Wi + bi   (fp32, ~roofline)
    gemm128<NIN, HID, 1><<<dim3(HID / 128, (BATCH * SEQ) / 128), 256>>>(x, Wi, bi, xi);

    // 2) recurrence: round-14 topology + warp-scope publication
    rnn_recurrence<<<128, 128, RNN_DSMEM>>>(Wh);

    // 3) y[b][s][o] = h @ Wo + bo    (fp32, ~roofline)
    gemm128<HID, NOUT, 2><<<dim3(NOUT / 128, (BATCH * SEQ) / 128), 256>>>(hh, Wo, bo, out);
}